// round 3
// baseline (speedup 1.0000x reference)
#include <cuda_runtime.h>

#define DEV_INLINE __device__ __forceinline__

namespace {
constexpr int Bb = 8, N_ = 196, D_ = 128, DFF_ = 256, C_ = 1000;
constexpr int M_ = Bb * N_;            // 1568 total rows
constexpr float NEG = -1e30f;
}

__device__ float g_h[M_ * D_];
__device__ float g_xn[M_ * D_];
__device__ float g_q[M_ * D_];
__device__ float g_k[M_ * D_];
__device__ float g_vt[Bb * D_ * N_];   // v transposed per batch: [b][d][n]
__device__ float g_ff[M_ * DFF_];
__device__ float g_pool[Bb * D_];

DEV_INLINE float warpMax(float v) {
#pragma unroll
    for (int m = 16; m > 0; m >>= 1)
        v = fmaxf(v, __shfl_xor_sync(0xffffffffu, v, m));
    return v;
}

// ============================================================
// Big-tile GEMM: out[m,n] = max_k(A[m,k] + W[n,k]), K=128
// BM=64, BN=64, BK=32, 256 threads, per-thread 4x4 (float4 LDS both sides)
// MODE 0: qkv fused (A=g_xn, N=384 -> q|k|vt)
// MODE 2: ff1 (A=g_xn, W=ff1_W 256x128, tau fused)
// ============================================================
template <int MODE>
__global__ void __launch_bounds__(256) gemmA_kernel(
    const float* __restrict__ W0, const float* __restrict__ W1,
    const float* __restrict__ W2, const float* __restrict__ tau) {
    __shared__ __align__(16) float As[32][68];
    __shared__ __align__(16) float Ws[32][68];
    const int tid = threadIdx.x;
    const int m0 = blockIdx.x * 64;
    const int n0 = blockIdx.y * 64;

    const float* Ap = g_xn;
    const float* Wp;
    if (MODE == 0) {
        int sec = n0 >> 7;
        Wp = (sec == 0 ? W0 : (sec == 1 ? W1 : W2)) + (n0 & 127) * 128;
    } else {
        Wp = W0 + n0 * 128;
    }

    const int kq = tid & 7, l = tid >> 3;   // loader coords
    float acc[4][4];
#pragma unroll
    for (int r = 0; r < 4; r++)
#pragma unroll
        for (int c = 0; c < 4; c++) acc[r][c] = NEG;

    const int r0 = (tid >> 4) * 4, c0 = (tid & 15) * 4;

#pragma unroll
    for (int k0 = 0; k0 < 128; k0 += 32) {
        // A tile 64x32
#pragma unroll
        for (int p = 0; p < 2; p++) {
            int row = l + p * 32;
            int gm = m0 + row; if (gm > M_ - 1) gm = M_ - 1;
            float4 av = *(const float4*)(Ap + gm * 128 + k0 + kq * 4);
            As[kq * 4 + 0][row] = av.x; As[kq * 4 + 1][row] = av.y;
            As[kq * 4 + 2][row] = av.z; As[kq * 4 + 3][row] = av.w;
        }
        // W tile 64x32
#pragma unroll
        for (int p = 0; p < 2; p++) {
            int nl = l + p * 32;
            float4 wv = *(const float4*)(Wp + nl * 128 + k0 + kq * 4);
            Ws[kq * 4 + 0][nl] = wv.x; Ws[kq * 4 + 1][nl] = wv.y;
            Ws[kq * 4 + 2][nl] = wv.z; Ws[kq * 4 + 3][nl] = wv.w;
        }
        __syncthreads();
#pragma unroll
        for (int kk = 0; kk < 32; kk++) {
            float4 a = *(const float4*)&As[kk][r0];
            float4 w = *(const float4*)&Ws[kk][c0];
            float ar[4] = {a.x, a.y, a.z, a.w};
            float wr[4] = {w.x, w.y, w.z, w.w};
#pragma unroll
            for (int r = 0; r < 4; r++)
#pragma unroll
                for (int c = 0; c < 4; c++)
                    acc[r][c] = fmaxf(acc[r][c], ar[r] + wr[c]);
        }
        __syncthreads();
    }

    if (MODE == 0) {
#pragma unroll
        for (int r = 0; r < 4; r++) {
            int gm = m0 + r0 + r;
            if (gm < M_) {
                int b = gm / 196, i = gm - b * 196;
#pragma unroll
                for (int c = 0; c < 4; c++) {
                    int gn = n0 + c0 + c;
                    float v = acc[r][c];
                    if (gn < 128)       g_q[gm * 128 + gn] = v;
                    else if (gn < 256)  g_k[gm * 128 + (gn - 128)] = v;
                    else                g_vt[(b * 128 + (gn - 256)) * N_ + i] = v;
                }
            }
        }
    } else {
        float tv = tau[0];
#pragma unroll
        for (int r = 0; r < 4; r++) {
            int gm = m0 + r0 + r;
            if (gm < M_) {
#pragma unroll
                for (int c = 0; c < 4; c++)
                    g_ff[gm * 256 + n0 + c0 + c] = fmaxf(acc[r][c], tv);
            }
        }
    }
}

// ============================================================
// Fused attention: per block (16 q-rows, one batch):
// stage1: scores[16][224] = max_d(q+k) into smem (j>=196 -> ~-1e30)
// rowmax per row (valid j only)
// stage2: o[i,d] = max_j(scores+vt) - rowmax; pnorm; residual; pnorm
// 512 threads.
// ============================================================
__global__ void __launch_bounds__(512) attn_fused_kernel() {
    __shared__ __align__(16) float Qs[32][17];
    __shared__ __align__(16) float score_s[16][228];
    __shared__ __align__(16) float uni[32 * 228];   // Ks (stage1) / Ws2 (stage2)
    float (*Ks)[228]  = (float(*)[228])uni;
    float (*Ws2)[132] = (float(*)[132])uni;

    const int tid = threadIdx.x;
    const int b = blockIdx.y;
    const int i0 = blockIdx.x * 16;
    const float* Qp = g_q + b * N_ * D_;
    const float* Kp = g_k + b * N_ * D_;
    const float* Vp = g_vt + b * D_ * N_;

    // ---------- stage 1: scores ----------
    // thread map (448 active): r_grp = tid/56 (0..7) -> 2 rows; c_grp = tid%56 -> 4 cols
    const int r_grp = tid / 56;
    const int c_grp = tid - r_grp * 56;
    const bool act1 = tid < 448;
    const int s_r0 = r_grp * 2, s_c0 = c_grp * 4;

    float sacc[2][4];
#pragma unroll
    for (int r = 0; r < 2; r++)
#pragma unroll
        for (int c = 0; c < 4; c++) sacc[r][c] = NEG;

#pragma unroll
    for (int d0 = 0; d0 < 128; d0 += 32) {
        // Q tile 16x32
        if (tid < 128) {
            int l = tid >> 3, kq = tid & 7;
            int gi = i0 + l; if (gi > N_ - 1) gi = N_ - 1;
            float4 qv = *(const float4*)(Qp + gi * 128 + d0 + kq * 4);
            Qs[kq * 4 + 0][l] = qv.x; Qs[kq * 4 + 1][l] = qv.y;
            Qs[kq * 4 + 2][l] = qv.z; Qs[kq * 4 + 3][l] = qv.w;
        }
        // K tile 224x32 (rows j, NEG beyond 195)
#pragma unroll
        for (int p = 0; p < 4; p++) {
            int idx = p * 512 + tid;
            if (idx < 224 * 8) {
                int j = idx >> 3, kq = idx & 7;
                float4 kv = (j < N_) ? *(const float4*)(Kp + j * 128 + d0 + kq * 4)
                                     : make_float4(NEG, NEG, NEG, NEG);
                Ks[kq * 4 + 0][j] = kv.x; Ks[kq * 4 + 1][j] = kv.y;
                Ks[kq * 4 + 2][j] = kv.z; Ks[kq * 4 + 3][j] = kv.w;
            }
        }
        __syncthreads();
        if (act1) {
#pragma unroll
            for (int kk = 0; kk < 32; kk++) {
                float a0 = Qs[kk][s_r0], a1 = Qs[kk][s_r0 + 1];
                float4 w = *(const float4*)&Ks[kk][s_c0];
                sacc[0][0] = fmaxf(sacc[0][0], a0 + w.x);
                sacc[0][1] = fmaxf(sacc[0][1], a0 + w.y);
                sacc[0][2] = fmaxf(sacc[0][2], a0 + w.z);
                sacc[0][3] = fmaxf(sacc[0][3], a0 + w.w);
                sacc[1][0] = fmaxf(sacc[1][0], a1 + w.x);
                sacc[1][1] = fmaxf(sacc[1][1], a1 + w.y);
                sacc[1][2] = fmaxf(sacc[1][2], a1 + w.z);
                sacc[1][3] = fmaxf(sacc[1][3], a1 + w.w);
            }
        }
        __syncthreads();
    }
    if (act1) {
#pragma unroll
        for (int r = 0; r < 2; r++)
            *(float4*)&score_s[s_r0 + r][s_c0] =
                make_float4(sacc[r][0], sacc[r][1], sacc[r][2], sacc[r][3]);
    }
    __syncthreads();

    // ---------- rowmax (warp w owns row w) ----------
    const int wid = tid >> 5, lane = tid & 31;
    float rm = NEG;
#pragma unroll
    for (int t = 0; t < 7; t++) {
        int j = lane + t * 32;
        float s = (j < N_) ? score_s[wid][j] : NEG;
        rm = fmaxf(rm, s);
    }
    rm = warpMax(rm);

    // ---------- stage 2: out[16][128] ----------
    // warp w -> row w; lane -> cols lane*4..lane*4+3
    const int c0 = lane * 4;
    float acc[4] = {NEG, NEG, NEG, NEG};

#pragma unroll
    for (int t = 0; t < 7; t++) {
        int j0 = t * 32;
        // vt tile: Ws2[32 j][128 d]
#pragma unroll
        for (int p = 0; p < 2; p++) {
            int d = (tid >> 3) + p * 64;
            int kq = tid & 7;
            int j = j0 + kq * 4;
            float4 vv = (j + 3 < N_) ? *(const float4*)(Vp + d * N_ + j)
                        : make_float4((j + 0 < N_) ? Vp[d * N_ + j + 0] : NEG,
                                      (j + 1 < N_) ? Vp[d * N_ + j + 1] : NEG,
                                      (j + 2 < N_) ? Vp[d * N_ + j + 2] : NEG,
                                      (j + 3 < N_) ? Vp[d * N_ + j + 3] : NEG);
            Ws2[kq * 4 + 0][d] = vv.x; Ws2[kq * 4 + 1][d] = vv.y;
            Ws2[kq * 4 + 2][d] = vv.z; Ws2[kq * 4 + 3][d] = vv.w;
        }
        __syncthreads();
#pragma unroll
        for (int kk = 0; kk < 32; kk++) {
            float s = score_s[wid][j0 + kk];       // broadcast
            float4 w = *(const float4*)&Ws2[kk][c0];
            acc[0] = fmaxf(acc[0], s + w.x);
            acc[1] = fmaxf(acc[1], s + w.y);
            acc[2] = fmaxf(acc[2], s + w.z);
            acc[3] = fmaxf(acc[3], s + w.w);
        }
        __syncthreads();
    }

    // ---------- epilogue: -rowmax, pnorm, residual, pnorm ----------
    int i = i0 + wid;
    if (i < N_) {
        float o[4];
#pragma unroll
        for (int c = 0; c < 4; c++) o[c] = acc[c] - rm;
        float dm = warpMax(fmaxf(fmaxf(o[0], o[1]), fmaxf(o[2], o[3])));
        int base = (b * 196 + i) * 128 + c0;
        float nx[4];
#pragma unroll
        for (int c = 0; c < 4; c++)
            nx[c] = fmaxf(g_h[base + c], o[c] - dm);
        float dm2 = warpMax(fmaxf(fmaxf(nx[0], nx[1]), fmaxf(nx[2], nx[3])));
#pragma unroll
        for (int c = 0; c < 4; c++) {
            g_h[base + c] = nx[c];
            g_xn[base + c] = nx[c] - dm2;
        }
    }
}

// ============================================================
// Config B (split-K, 512 threads): BM=16, BN=128, BK=32 (embed, ff2)
// ============================================================
template <bool DO_RM>
DEV_INLINE void innerB(const float (&As)[32][18], const float (&Ws)[32][132],
                       float (&acc)[2][4], float (&rm)[2], int r0, int c0) {
#pragma unroll
    for (int kk = 0; kk < 32; kk++) {
        float a0 = As[kk][r0], a1 = As[kk][r0 + 1];
        float4 w = *(const float4*)&Ws[kk][c0];
        if (DO_RM) { rm[0] = fmaxf(rm[0], a0); rm[1] = fmaxf(rm[1], a1); }
        acc[0][0] = fmaxf(acc[0][0], a0 + w.x);
        acc[0][1] = fmaxf(acc[0][1], a0 + w.y);
        acc[0][2] = fmaxf(acc[0][2], a0 + w.z);
        acc[0][3] = fmaxf(acc[0][3], a0 + w.w);
        acc[1][0] = fmaxf(acc[1][0], a1 + w.x);
        acc[1][1] = fmaxf(acc[1][1], a1 + w.y);
        acc[1][2] = fmaxf(acc[1][2], a1 + w.z);
        acc[1][3] = fmaxf(acc[1][3], a1 + w.w);
    }
}

__global__ void __launch_bounds__(512) embed_kernel(
    const float* __restrict__ x, const float* __restrict__ eW,
    const float* __restrict__ pos) {
    __shared__ __align__(16) float As[2][32][18];
    __shared__ __align__(16) float Ws[2][32][132];
    __shared__ float red[16][132];
    const int tid = threadIdx.x;
    const int wg = tid >> 8;
    const int wtid = tid & 255;
    const int m0 = blockIdx.x * 16;
    const int kq = wtid & 7, l = wtid >> 3;
    float acc[2][4];
    float rm[2];
#pragma unroll
    for (int r = 0; r < 2; r++)
#pragma unroll
        for (int c = 0; c < 4; c++) acc[r][c] = NEG;
    const int r0 = (wtid >> 5) * 2, c0 = (wtid & 31) * 4;
    const int kbase = wg * 128;

#pragma unroll
    for (int t = 0; t < 4; t++) {
        int k0 = kbase + t * 32;
        if (wtid < 128) {
            int gm = m0 + l;
            int b = gm / 196, n = gm - b * 196;
            int gy = n / 14, gx = n - gy * 14;
            int k = k0 + kq * 4;
            int py = k >> 4, px = k & 15;
            float4 av = *(const float4*)(x + b * 50176 + (gy * 16 + py) * 224 + gx * 16 + px);
            As[wg][kq * 4 + 0][l] = av.x; As[wg][kq * 4 + 1][l] = av.y;
            As[wg][kq * 4 + 2][l] = av.z; As[wg][kq * 4 + 3][l] = av.w;
        }
#pragma unroll
        for (int p = 0; p < 4; p++) {
            int nl = l + p * 32;
            float4 wv = *(const float4*)(eW + nl * 256 + k0 + kq * 4);
            Ws[wg][kq * 4 + 0][nl] = wv.x; Ws[wg][kq * 4 + 1][nl] = wv.y;
            Ws[wg][kq * 4 + 2][nl] = wv.z; Ws[wg][kq * 4 + 3][nl] = wv.w;
        }
        __syncthreads();
        innerB<false>(As[wg], Ws[wg], acc, rm, r0, c0);
        __syncthreads();
    }

    if (wg == 1) {
#pragma unroll
        for (int r = 0; r < 2; r++)
#pragma unroll
            for (int c = 0; c < 4; c++) red[r0 + r][c0 + c] = acc[r][c];
    }
    __syncthreads();
    if (wg == 1) return;

#pragma unroll
    for (int r = 0; r < 2; r++) {
        int gm = m0 + r0 + r;
        int n = gm % 196;
        float h[4];
#pragma unroll
        for (int c = 0; c < 4; c++)
            h[c] = fmaxf(acc[r][c], red[r0 + r][c0 + c]) + pos[n * 128 + c0 + c];
        float dm = warpMax(fmaxf(fmaxf(h[0], h[1]), fmaxf(h[2], h[3])));
        int base = gm * 128 + c0;
#pragma unroll
        for (int c = 0; c < 4; c++) {
            g_h[base + c] = h[c];
            g_xn[base + c] = h[c] - dm;
        }
    }
}

__global__ void __launch_bounds__(512) ff2_kernel(const float* __restrict__ W) {
    __shared__ __align__(16) float As[2][32][18];
    __shared__ __align__(16) float Ws[2][32][132];
    __shared__ float red[16][132];
    const int tid = threadIdx.x;
    const int wg = tid >> 8;
    const int wtid = tid & 255;
    const int m0 = blockIdx.x * 16;
    const int kq = wtid & 7, l = wtid >> 3;
    float acc[2][4];
    float rm[2];
#pragma unroll
    for (int r = 0; r < 2; r++)
#pragma unroll
        for (int c = 0; c < 4; c++) acc[r][c] = NEG;
    const int r0 = (wtid >> 5) * 2, c0 = (wtid & 31) * 4;
    const int kbase = wg * 128;

#pragma unroll
    for (int t = 0; t < 4; t++) {
        int k0 = kbase + t * 32;
        if (wtid < 128) {
            float4 av = *(const float4*)(g_ff + (m0 + l) * 256 + k0 + kq * 4);
            As[wg][kq * 4 + 0][l] = av.x; As[wg][kq * 4 + 1][l] = av.y;
            As[wg][kq * 4 + 2][l] = av.z; As[wg][kq * 4 + 3][l] = av.w;
        }
#pragma unroll
        for (int p = 0; p < 4; p++) {
            int nl = l + p * 32;
            float4 wv = *(const float4*)(W + nl * 256 + k0 + kq * 4);
            Ws[wg][kq * 4 + 0][nl] = wv.x; Ws[wg][kq * 4 + 1][nl] = wv.y;
            Ws[wg][kq * 4 + 2][nl] = wv.z; Ws[wg][kq * 4 + 3][nl] = wv.w;
        }
        __syncthreads();
        innerB<false>(As[wg], Ws[wg], acc, rm, r0, c0);
        __syncthreads();
    }

    if (wg == 1) {
#pragma unroll
        for (int r = 0; r < 2; r++)
#pragma unroll
            for (int c = 0; c < 4; c++) red[r0 + r][c0 + c] = acc[r][c];
    }
    __syncthreads();
    if (wg == 1) return;

#pragma unroll
    for (int r = 0; r < 2; r++) {
        int gm = m0 + r0 + r;
#pragma unroll
        for (int c = 0; c < 4; c++)
            acc[r][c] = fmaxf(acc[r][c], red[r0 + r][c0 + c]);
        float dm = warpMax(fmaxf(fmaxf(acc[r][0], acc[r][1]), fmaxf(acc[r][2], acc[r][3])));
        int base = gm * 128 + c0;
        float nx[4];
#pragma unroll
        for (int c = 0; c < 4; c++)
            nx[c] = fmaxf(g_h[base + c], acc[r][c] - dm);
        float dm2 = warpMax(fmaxf(fmaxf(nx[0], nx[1]), fmaxf(nx[2], nx[3])));
#pragma unroll
        for (int c = 0; c < 4; c++) {
            g_h[base + c] = nx[c];
            g_xn[base + c] = nx[c] - dm2;
        }
    }
}

__global__ void __launch_bounds__(512) pool_kernel() {
    __shared__ float sm[4][128];
    int b = blockIdx.x;
    int d = threadIdx.x & 127;
    int q = threadIdx.x >> 7;
    float m = NEG;
    for (int n = q; n < N_; n += 4)
        m = fmaxf(m, g_h[(b * N_ + n) * D_ + d]);
    sm[q][d] = m;
    __syncthreads();
    if (q == 0) {
        m = fmaxf(fmaxf(sm[0][d], sm[1][d]), fmaxf(sm[2][d], sm[3][d]));
        g_pool[b * D_ + d] = m;
    }
}

__global__ void __launch_bounds__(256) head_kernel(
    const float* __restrict__ hW, const float* __restrict__ ls,
    float* __restrict__ out) {
    __shared__ float sp[128];
    const int b = blockIdx.y;
    const int tid = threadIdx.x;
    if (tid < 128) sp[tid] = g_pool[b * 128 + tid];
    __syncthreads();
    int c = blockIdx.x * 256 + tid;
    if (c < C_) {
        float acc = NEG;
#pragma unroll 8
        for (int d = 0; d < 128; d += 4) {
            float4 w = *(const float4*)(hW + c * 128 + d);
            acc = fmaxf(acc, sp[d + 0] + w.x);
            acc = fmaxf(acc, sp[d + 1] + w.y);
            acc = fmaxf(acc, sp[d + 2] + w.z);
            acc = fmaxf(acc, sp[d + 3] + w.w);
        }
        out[b * C_ + c] = acc * ls[0];
    }
}

extern "C" void kernel_launch(void* const* d_in, const int* in_sizes, int n_in,
                              void* d_out, int out_size) {
    const float* x   = (const float*)d_in[0];
    const float* eW  = (const float*)d_in[1];
    const float* pos = (const float*)d_in[2];
    const float* qW[2]  = {(const float*)d_in[3],  (const float*)d_in[9]};
    const float* kW[2]  = {(const float*)d_in[4],  (const float*)d_in[10]};
    const float* vW[2]  = {(const float*)d_in[5],  (const float*)d_in[11]};
    const float* f1[2]  = {(const float*)d_in[6],  (const float*)d_in[12]};
    const float* f2[2]  = {(const float*)d_in[7],  (const float*)d_in[13]};
    const float* tau[2] = {(const float*)d_in[8],  (const float*)d_in[14]};
    const float* hW = (const float*)d_in[15];
    const float* ls = (const float*)d_in[16];
    float* out = (float*)d_out;

    embed_kernel<<<98, 512>>>(x, eW, pos);
    for (int l = 0; l < 2; l++) {
        gemmA_kernel<0><<<dim3(25, 6), 256>>>(qW[l], kW[l], vW[l], nullptr);   // q,k,vt
        attn_fused_kernel<<<dim3(13, 8), 512>>>();                             // scores+attnout fused
        gemmA_kernel<2><<<dim3(25, 4), 256>>>(f1[l], nullptr, nullptr, tau[l]); // ff1 + tau
        ff2_kernel<<<98, 512>>>(f2[l]);
    }
    pool_kernel<<<8, 512>>>();
    head_kernel<<<dim3(4, 8), 256>>>(hW, ls, out);
}